// round 4
// baseline (speedup 1.0000x reference)
#include <cuda_runtime.h>
#include <cuda_bf16.h>
#include <math.h>
#include <stdint.h>
#include <string.h>

// ---------------------------------------------------------------------------
// Problem constants
// ---------------------------------------------------------------------------
#define BB 16
#define LL 4096
#define HH 512
#define PP 256
#define MM (BB * LL)          // 65536 rows
#define KK 512                // GEMM K for both GEMMs
#define CH 128                // scan chunk length
#define NCHUNK (LL / CH)      // 32
#define LN_EPS 1e-6f

// GEMM tiling
#define BM 128
#define BN 256
#define BK 32
#define NKIT (KK / BK)        // 16
#define BKP 40                // A smem k-stride (bf16 elems), 80 B rows
#define BNP 264               // B smem n-stride (bf16 elems), 528 B rows
// stage byte offsets
#define SA_H 0
#define SA_L 10240
#define SB_H 20480
#define SB_L 37376
#define STAGE_BYTES 54272

// ---------------------------------------------------------------------------
// Scratch (static __device__ — no allocation allowed)
// ---------------------------------------------------------------------------
__device__ float g_A1[(size_t)MM * KK];       // Bu (fp32)
__device__ float g_ys[(size_t)MM * HH];       // ys scratch
__device__ __nv_bfloat16 g_XSh[(size_t)MM * KK];  // xs hi plane
__device__ __nv_bfloat16 g_XSl[(size_t)MM * KK];  // xs lo plane
__device__ __nv_bfloat16 g_W1h[KK * HH];      // W1 [k=h][n=p|256+p] hi
__device__ __nv_bfloat16 g_W1l[KK * HH];
__device__ __nv_bfloat16 g_W2h[KK * HH];      // W2 [k=p|256+p][n=h] hi
__device__ __nv_bfloat16 g_W2l[KK * HH];
__device__ float g_lbar[2 * PP];
__device__ float g_aC[2 * PP];
__device__ float g_coef[2 * PP];
__device__ float g_carry[BB * NCHUNK * 2 * PP];
__device__ float g_prefix[BB * NCHUNK * 2 * PP];

// ---------------------------------------------------------------------------
// PTX helpers
// ---------------------------------------------------------------------------
__device__ __forceinline__ uint32_t s2u(const void* p) {
    return (uint32_t)__cvta_generic_to_shared(p);
}
__device__ __forceinline__ void ldsm4(uint32_t* r, uint32_t a) {
    asm volatile("ldmatrix.sync.aligned.m8n8.x4.shared.b16 {%0,%1,%2,%3},[%4];\n"
                 : "=r"(r[0]), "=r"(r[1]), "=r"(r[2]), "=r"(r[3]) : "r"(a));
}
__device__ __forceinline__ void ldsm4t(uint32_t* r, uint32_t a) {
    asm volatile("ldmatrix.sync.aligned.m8n8.x4.trans.shared.b16 {%0,%1,%2,%3},[%4];\n"
                 : "=r"(r[0]), "=r"(r[1]), "=r"(r[2]), "=r"(r[3]) : "r"(a));
}
__device__ __forceinline__ void mma16816(float* d, const uint32_t* a, uint32_t b0, uint32_t b1) {
    asm volatile("mma.sync.aligned.m16n8k16.row.col.f32.bf16.bf16.f32 "
                 "{%0,%1,%2,%3},{%4,%5,%6,%7},{%8,%9},{%0,%1,%2,%3};\n"
                 : "+f"(d[0]), "+f"(d[1]), "+f"(d[2]), "+f"(d[3])
                 : "r"(a[0]), "r"(a[1]), "r"(a[2]), "r"(a[3]), "r"(b0), "r"(b1));
}
__device__ __forceinline__ void cp_async16(uint32_t dst, const void* src) {
    asm volatile("cp.async.cg.shared.global [%0], [%1], 16;" :: "r"(dst), "l"(src));
}
__device__ __forceinline__ void cp_commit() {
    asm volatile("cp.async.commit_group;" ::: "memory");
}
__device__ __forceinline__ void cp_wait1() {
    asm volatile("cp.async.wait_group 1;" ::: "memory");
}
__device__ __forceinline__ void cp_wait0() {
    asm volatile("cp.async.wait_group 0;" ::: "memory");
}

// ---------------------------------------------------------------------------
// Setup: per-p scalars
// ---------------------------------------------------------------------------
__global__ void k_setup_small(const float* __restrict__ log_lambda_re,
                              const float* __restrict__ lambda_im,
                              const float* __restrict__ log_step) {
    int p = threadIdx.x;
    if (p >= PP) return;
    float lam_re = -expf(log_lambda_re[p]);
    float lam_im = lambda_im[p];
    float st = expf(log_step[p]);
    float ar = lam_re * st, ai = lam_im * st;
    float e = expf(ar);
    float lbr = e * cosf(ai);
    float lbi = e * sinf(ai);
    g_lbar[p] = lbr; g_lbar[PP + p] = lbi;
    float nr = lbr - 1.0f, ni = lbi;
    float d2 = lam_re * lam_re + lam_im * lam_im;
    g_coef[p]      = (nr * lam_re + ni * lam_im) / d2;
    g_coef[PP + p] = (ni * lam_re - nr * lam_im) / d2;
    float sr = lbr, si = lbi;
    #pragma unroll
    for (int i = 0; i < 7; i++) {
        float r2 = sr * sr - si * si;
        float i2 = 2.0f * sr * si;
        sr = r2; si = i2;
    }
    g_aC[p] = sr; g_aC[PP + p] = si;
}

// ---------------------------------------------------------------------------
// Setup: folded weights [k][n] row-major, bf16 hi/lo planes
// ---------------------------------------------------------------------------
__device__ __forceinline__ void bf16_split(float v, __nv_bfloat16& h, __nv_bfloat16& l) {
    h = __float2bfloat16_rn(v);
    l = __float2bfloat16_rn(v - __bfloat162float(h));
}

__global__ void k_setup_W(const float* __restrict__ B_re, const float* __restrict__ B_im,
                          const float* __restrict__ C_re, const float* __restrict__ C_im) {
    int idx = blockIdx.x * blockDim.x + threadIdx.x;
    if (idx >= PP * HH) return;
    int p = idx / HH;
    int h = idx % HH;
    float cr = g_coef[p], ci = g_coef[PP + p];
    float br = B_re[p * HH + h], bi = B_im[p * HH + h];
    float w1r = cr * br - ci * bi;
    float w1i = cr * bi + ci * br;
    // GEMM1: k = h, n = p (re) / 256+p (im)
    bf16_split(w1r, g_W1h[h * KK + p],      g_W1l[h * KK + p]);
    bf16_split(w1i, g_W1h[h * KK + PP + p], g_W1l[h * KK + PP + p]);
    // GEMM2: k = p (re) / 256+p (im), n = h
    bf16_split( 2.0f * C_re[h * PP + p], g_W2h[p * HH + h],        g_W2l[p * HH + h]);
    bf16_split(-2.0f * C_im[h * PP + p], g_W2h[(PP + p) * HH + h], g_W2l[(PP + p) * HH + h]);
}

// ---------------------------------------------------------------------------
// Pipelined mma.sync GEMM with 3xBF16 split.
// C[M,512] = A[M,512] @ W[512,512]  (W pre-split [k][n] bf16 planes)
// SPLIT_A: A is fp32, split in-kernel (LDG->regs->STS).
// else:    A is pre-split bf16 planes (pure cp.async).
// Grid (2, 512), 512 threads, warp tile 64x32.
// ---------------------------------------------------------------------------
template <bool SPLIT_A>
__global__ __launch_bounds__(512, 1) void k_gemm(
    const float* __restrict__ Af,
    const __nv_bfloat16* __restrict__ Aph,
    const __nv_bfloat16* __restrict__ Apl,
    const __nv_bfloat16* __restrict__ Wh,
    const __nv_bfloat16* __restrict__ Wl,
    float* __restrict__ C)
{
    extern __shared__ __align__(16) char dsm[];
    uint32_t smem = s2u(dsm);

    int tid = threadIdx.x;
    int lane = tid & 31, w = tid >> 5;
    int wm = (w & 1) * 64;
    int wn = (w >> 1) * 32;
    int mtile = blockIdx.y * BM;
    int ntile = blockIdx.x * BN;

    // ldmatrix per-lane offsets
    int a_r = lane & 15;
    int a_c = (lane >> 4) * 8;
    int b_r = (lane & 7) + ((lane >> 3) & 1) * 8;
    int b_c = (lane >> 4) * 8;

    float acc[4][4][4];
    #pragma unroll
    for (int i = 0; i < 4; i++)
        #pragma unroll
        for (int j = 0; j < 4; j++)
            #pragma unroll
            for (int c = 0; c < 4; c++) acc[i][j][c] = 0.0f;

    // load index precompute
    int b_row = 0, b_c16 = 0;           // B: 2 chunks/thread/plane
    int ap_row = tid >> 2, ap_c16 = tid & 3;   // A planes: 1 chunk/thread/plane
    int af_row0 = tid >> 3, af_c4 = tid & 7;   // A fp32: 2 float4/thread

    float4 areg[2];

    // ---- helpers as lambdas ----
    auto load_B = [&](int it, uint32_t stage) {
        const __nv_bfloat16* bh = Wh + (size_t)(it * BK) * 512 + ntile;
        const __nv_bfloat16* bl = Wl + (size_t)(it * BK) * 512 + ntile;
        #pragma unroll
        for (int i = 0; i < 2; i++) {
            int idx = tid + 512 * i;
            int row = idx >> 5, c16 = idx & 31;
            uint32_t d = (uint32_t)(row * 528 + c16 * 16);
            cp_async16(stage + SB_H + d, (const char*)(bh + (size_t)row * 512) + c16 * 16);
            cp_async16(stage + SB_L + d, (const char*)(bl + (size_t)row * 512) + c16 * 16);
        }
    };
    auto load_Ap = [&](int it, uint32_t stage) {
        uint32_t d = (uint32_t)(ap_row * 80 + ap_c16 * 16);
        const char* sh = (const char*)(Aph + (size_t)(mtile + ap_row) * 512 + it * BK) + ap_c16 * 16;
        const char* sl = (const char*)(Apl + (size_t)(mtile + ap_row) * 512 + it * BK) + ap_c16 * 16;
        cp_async16(stage + SA_H + d, sh);
        cp_async16(stage + SA_L + d, sl);
    };
    auto ldg_Af = [&](int it) {
        #pragma unroll
        for (int i = 0; i < 2; i++) {
            int row = af_row0 + 64 * i;
            areg[i] = *reinterpret_cast<const float4*>(
                Af + (size_t)(mtile + row) * 512 + it * BK + af_c4 * 4);
        }
    };
    auto sts_Af = [&](uint32_t stage) {
        #pragma unroll
        for (int i = 0; i < 2; i++) {
            int row = af_row0 + 64 * i;
            float4 v = areg[i];
            __nv_bfloat162 h0 = __floats2bfloat162_rn(v.x, v.y);
            __nv_bfloat162 h1 = __floats2bfloat162_rn(v.z, v.w);
            float2 hf0 = __bfloat1622float2(h0);
            float2 hf1 = __bfloat1622float2(h1);
            __nv_bfloat162 l0 = __floats2bfloat162_rn(v.x - hf0.x, v.y - hf0.y);
            __nv_bfloat162 l1 = __floats2bfloat162_rn(v.z - hf1.x, v.w - hf1.y);
            uint32_t hh0, hh1, ll0, ll1;
            memcpy(&hh0, &h0, 4); memcpy(&hh1, &h1, 4);
            memcpy(&ll0, &l0, 4); memcpy(&ll1, &l1, 4);
            uint32_t d = (uint32_t)(row * 80 + af_c4 * 8);
            asm volatile("st.shared.v2.b32 [%0], {%1, %2};"
                         :: "r"(stage + SA_H + d), "r"(hh0), "r"(hh1) : "memory");
            asm volatile("st.shared.v2.b32 [%0], {%1, %2};"
                         :: "r"(stage + SA_L + d), "r"(ll0), "r"(ll1) : "memory");
        }
    };
    (void)b_row; (void)b_c16;

    uint32_t stg[2] = {smem, smem + STAGE_BYTES};

    // ---- prologue: stage 0 ----
    load_B(0, stg[0]);
    if (SPLIT_A) { ldg_Af(0); sts_Af(stg[0]); }
    else load_Ap(0, stg[0]);
    cp_commit();

    for (int it = 0; it < NKIT; it++) {
        int s = it & 1;
        bool nxt = (it + 1 < NKIT);
        if (nxt) {
            load_B(it + 1, stg[s ^ 1]);
            if (SPLIT_A) ldg_Af(it + 1);
            else load_Ap(it + 1, stg[s ^ 1]);
            cp_commit();
        }
        if (nxt) cp_wait1(); else cp_wait0();
        __syncthreads();
        if (nxt && SPLIT_A) sts_Af(stg[s ^ 1]);

        uint32_t sA_h = stg[s] + SA_H;
        uint32_t sA_l = stg[s] + SA_L;
        uint32_t sB_h = stg[s] + SB_H;
        uint32_t sB_l = stg[s] + SB_L;

        #pragma unroll
        for (int ks = 0; ks < 2; ks++) {
            int ko = ks * 16;
            uint32_t bh[2][4], bl[2][4], ah[4][4], al[4][4];
            #pragma unroll
            for (int j2 = 0; j2 < 2; j2++)
                ldsm4t(bh[j2], sB_h + (uint32_t)(((ko + b_r) * BNP + wn + j2 * 16 + b_c) * 2));
            #pragma unroll
            for (int i = 0; i < 4; i++)
                ldsm4(ah[i], sA_h + (uint32_t)(((wm + i * 16 + a_r) * BKP + ko + a_c) * 2));
            #pragma unroll
            for (int i = 0; i < 4; i++)
                #pragma unroll
                for (int j = 0; j < 4; j++)
                    mma16816(acc[i][j], ah[i], bh[j >> 1][(j & 1) * 2], bh[j >> 1][(j & 1) * 2 + 1]);
            #pragma unroll
            for (int i = 0; i < 4; i++)
                ldsm4(al[i], sA_l + (uint32_t)(((wm + i * 16 + a_r) * BKP + ko + a_c) * 2));
            #pragma unroll
            for (int i = 0; i < 4; i++)
                #pragma unroll
                for (int j = 0; j < 4; j++)
                    mma16816(acc[i][j], al[i], bh[j >> 1][(j & 1) * 2], bh[j >> 1][(j & 1) * 2 + 1]);
            #pragma unroll
            for (int j2 = 0; j2 < 2; j2++)
                ldsm4t(bl[j2], sB_l + (uint32_t)(((ko + b_r) * BNP + wn + j2 * 16 + b_c) * 2));
            #pragma unroll
            for (int i = 0; i < 4; i++)
                #pragma unroll
                for (int j = 0; j < 4; j++)
                    mma16816(acc[i][j], ah[i], bl[j >> 1][(j & 1) * 2], bl[j >> 1][(j & 1) * 2 + 1]);
        }
        __syncthreads();
    }

    // ---- store C (fp32) ----
    #pragma unroll
    for (int i = 0; i < 4; i++) {
        int r0 = mtile + wm + i * 16 + (lane >> 2);
        int c0 = ntile + wn + (lane & 3) * 2;
        #pragma unroll
        for (int j = 0; j < 4; j++) {
            *reinterpret_cast<float2*>(&C[(size_t)r0 * 512 + c0 + j * 8]) =
                make_float2(acc[i][j][0], acc[i][j][1]);
            *reinterpret_cast<float2*>(&C[(size_t)(r0 + 8) * 512 + c0 + j * 8]) =
                make_float2(acc[i][j][2], acc[i][j][3]);
        }
    }
}

// ---------------------------------------------------------------------------
// Scan phase 1: per-chunk carry (read-only over Bu)
// ---------------------------------------------------------------------------
__global__ __launch_bounds__(256) void k_scan_carry() {
    int blk = blockIdx.x;
    int b = blk / NCHUNK;
    int j = blk % NCHUNK;
    int p = threadIdx.x;
    float ar = g_lbar[p], ai = g_lbar[PP + p];
    float sr = 0.0f, si = 0.0f;
    size_t base = ((size_t)b * LL + (size_t)j * CH) * KK + p;
    #pragma unroll 4
    for (int t = 0; t < CH; t++) {
        float br = g_A1[base + (size_t)t * KK];
        float bi = g_A1[base + (size_t)t * KK + PP];
        float nr = fmaf(ar, sr, fmaf(-ai, si, br));
        float ni = fmaf(ar, si, fmaf(ai, sr, bi));
        sr = nr; si = ni;
    }
    g_carry[(size_t)blk * KK + p]      = sr;
    g_carry[(size_t)blk * KK + PP + p] = si;
}

// ---------------------------------------------------------------------------
// Scan phase 2: prefix over chunk carries (tiny)
// ---------------------------------------------------------------------------
__global__ void k_scan_prefix() {
    int b = blockIdx.x;
    int p = threadIdx.x;
    float ar = g_aC[p], ai = g_aC[PP + p];
    float sr = 0.0f, si = 0.0f;
    for (int j = 0; j < NCHUNK; j++) {
        size_t o = (size_t)(b * NCHUNK + j) * KK + p;
        g_prefix[o]      = sr;
        g_prefix[o + PP] = si;
        float cr = g_carry[o], ci = g_carry[o + PP];
        float nr = fmaf(ar, sr, fmaf(-ai, si, cr));
        float ni = fmaf(ar, si, fmaf(ai, sr, ci));
        sr = nr; si = ni;
    }
}

// ---------------------------------------------------------------------------
// Scan phase 3: recompute seeded with prefix, write xs as bf16 hi/lo planes
// ---------------------------------------------------------------------------
__global__ __launch_bounds__(256) void k_scan_apply() {
    int blk = blockIdx.x;
    int b = blk / NCHUNK;
    int j = blk % NCHUNK;
    int p = threadIdx.x;
    float ar = g_lbar[p], ai = g_lbar[PP + p];
    size_t po = (size_t)blk * KK + p;
    float sr = g_prefix[po], si = g_prefix[po + PP];
    size_t base = ((size_t)b * LL + (size_t)j * CH) * KK + p;
    #pragma unroll 4
    for (int t = 0; t < CH; t++) {
        float br = g_A1[base + (size_t)t * KK];
        float bi = g_A1[base + (size_t)t * KK + PP];
        float nr = fmaf(ar, sr, fmaf(-ai, si, br));
        float ni = fmaf(ar, si, fmaf(ai, sr, bi));
        sr = nr; si = ni;
        size_t o = base + (size_t)t * KK;
        __nv_bfloat16 h, l;
        h = __float2bfloat16_rn(sr); l = __float2bfloat16_rn(sr - __bfloat162float(h));
        g_XSh[o] = h; g_XSl[o] = l;
        h = __float2bfloat16_rn(si); l = __float2bfloat16_rn(si - __bfloat162float(h));
        g_XSh[o + PP] = h; g_XSl[o + PP] = l;
    }
}

// ---------------------------------------------------------------------------
// Epilogue: y = gelu_tanh(ys + x*D); z = x + y; LayerNorm over H
// ---------------------------------------------------------------------------
__global__ __launch_bounds__(256) void k_epilogue(const float* __restrict__ x,
                                                  const float* __restrict__ D,
                                                  const float* __restrict__ ln_scale,
                                                  const float* __restrict__ ln_bias,
                                                  float* __restrict__ out) {
    int row = blockIdx.x;
    int tid = threadIdx.x;
    const float* ysr = g_ys + (size_t)row * HH;
    const float* xr  = x    + (size_t)row * HH;
    float zv[2];
    float sum = 0.0f, sum2 = 0.0f;
    #pragma unroll
    for (int e = 0; e < 2; e++) {
        int h = tid + e * 256;
        float xv = xr[h];
        float y = ysr[h] + xv * D[h];
        float y3 = y * y * y;
        float u = 0.7978845608028654f * (y + 0.044715f * y3);
        float g = 0.5f * y * (1.0f + tanhf(u));
        float z = xv + g;
        zv[e] = z;
        sum += z; sum2 += z * z;
    }
    __shared__ float s1[8], s2[8], stats[2];
    #pragma unroll
    for (int off = 16; off > 0; off >>= 1) {
        sum  += __shfl_down_sync(0xFFFFFFFFu, sum, off);
        sum2 += __shfl_down_sync(0xFFFFFFFFu, sum2, off);
    }
    int lane = tid & 31, wid = tid >> 5;
    if (lane == 0) { s1[wid] = sum; s2[wid] = sum2; }
    __syncthreads();
    if (tid == 0) {
        float a = 0.0f, b = 0.0f;
        #pragma unroll
        for (int i = 0; i < 8; i++) { a += s1[i]; b += s2[i]; }
        float mean = a * (1.0f / HH);
        float var = b * (1.0f / HH) - mean * mean;
        stats[0] = mean;
        stats[1] = rsqrtf(var + LN_EPS);
    }
    __syncthreads();
    float mean = stats[0], rstd = stats[1];
    float* outr = out + (size_t)row * HH;
    #pragma unroll
    for (int e = 0; e < 2; e++) {
        int h = tid + e * 256;
        outr[h] = (zv[e] - mean) * rstd * ln_scale[h] + ln_bias[h];
    }
}

// ---------------------------------------------------------------------------
// Launch
// ---------------------------------------------------------------------------
extern "C" void kernel_launch(void* const* d_in, const int* in_sizes, int n_in,
                              void* d_out, int out_size) {
    const float* x             = (const float*)d_in[0];
    const float* log_lambda_re = (const float*)d_in[1];
    const float* lambda_im     = (const float*)d_in[2];
    const float* B_re          = (const float*)d_in[3];
    const float* B_im          = (const float*)d_in[4];
    const float* C_re          = (const float*)d_in[5];
    const float* C_im          = (const float*)d_in[6];
    const float* D             = (const float*)d_in[7];
    const float* log_step      = (const float*)d_in[8];
    const float* ln_scale      = (const float*)d_in[9];
    const float* ln_bias       = (const float*)d_in[10];
    float* out = (float*)d_out;

    k_setup_small<<<1, 256>>>(log_lambda_re, lambda_im, log_step);
    k_setup_W<<<(PP * HH + 255) / 256, 256>>>(B_re, B_im, C_re, C_im);

    float *gA1, *gys;
    __nv_bfloat16 *gXSh, *gXSl, *gW1h, *gW1l, *gW2h, *gW2l;
    cudaGetSymbolAddress((void**)&gA1, g_A1);
    cudaGetSymbolAddress((void**)&gys, g_ys);
    cudaGetSymbolAddress((void**)&gXSh, g_XSh);
    cudaGetSymbolAddress((void**)&gXSl, g_XSl);
    cudaGetSymbolAddress((void**)&gW1h, g_W1h);
    cudaGetSymbolAddress((void**)&gW1l, g_W1l);
    cudaGetSymbolAddress((void**)&gW2h, g_W2h);
    cudaGetSymbolAddress((void**)&gW2l, g_W2l);

    int dyn = 2 * STAGE_BYTES;  // 108544
    cudaFuncSetAttribute(k_gemm<true>,  cudaFuncAttributeMaxDynamicSharedMemorySize, dyn);
    cudaFuncSetAttribute(k_gemm<false>, cudaFuncAttributeMaxDynamicSharedMemorySize, dyn);

    dim3 grid(HH / BN, MM / BM);   // (2, 512)

    // GEMM1: Bu = x @ W1 (A fp32, split in-kernel)
    k_gemm<true><<<grid, 512, dyn>>>(x, nullptr, nullptr, gW1h, gW1l, gA1);

    // chunked scan over L (emits xs bf16 planes)
    k_scan_carry<<<BB * NCHUNK, 256>>>();
    k_scan_prefix<<<BB, 256>>>();
    k_scan_apply<<<BB * NCHUNK, 256>>>();

    // GEMM2: ys = xs @ W2 (A pre-split planes)
    k_gemm<false><<<grid, 512, dyn>>>(nullptr, gXSh, gXSl, gW2h, gW2l, gys);

    // epilogue
    k_epilogue<<<MM, 256>>>(x, D, ln_scale, ln_bias, out);
}

// round 5
// speedup vs baseline: 1.5993x; 1.5993x over previous
#include <cuda_runtime.h>
#include <cuda_fp16.h>
#include <math.h>
#include <stdint.h>
#include <string.h>

// ---------------------------------------------------------------------------
// Problem constants
// ---------------------------------------------------------------------------
#define BB 16
#define LL 4096
#define HH 512
#define PP 256
#define MM (BB * LL)          // 65536 rows
#define KK 512                // GEMM K for both GEMMs
#define CH 128                // scan chunk length
#define NCHUNK (LL / CH)      // 32
#define LN_EPS 1e-6f

// GEMM tiling (round-2 proven geometry)
#define BM 128
#define BN 128
#define BK 32
#define BKP 40    // padded A smem k-stride (fp16 elems)
#define BNP 136   // padded B smem n-stride (fp16 elems)

// ---------------------------------------------------------------------------
// Scratch (static __device__ — no allocation allowed)
// ---------------------------------------------------------------------------
__device__ float  g_A1[(size_t)MM * KK];   // Bu (fp32)
__device__ float  g_ys[(size_t)MM * HH];   // ys scratch
__device__ __half g_XS[(size_t)MM * KK];   // xs (fp16, written by scan_apply)
__device__ __half g_W1[KK * HH];           // W1 [k=h][n=p|256+p]
__device__ __half g_W2[KK * HH];           // W2 [k=p|256+p][n=h]
__device__ float g_lbar[2 * PP];
__device__ float g_aC[2 * PP];
__device__ float g_coef[2 * PP];
__device__ float g_carry[BB * NCHUNK * 2 * PP];
__device__ float g_prefix[BB * NCHUNK * 2 * PP];

// ---------------------------------------------------------------------------
// PTX helpers
// ---------------------------------------------------------------------------
__device__ __forceinline__ uint32_t s2u(const void* p) {
    return (uint32_t)__cvta_generic_to_shared(p);
}
__device__ __forceinline__ void ldsm4(uint32_t* r, uint32_t a) {
    asm volatile("ldmatrix.sync.aligned.m8n8.x4.shared.b16 {%0,%1,%2,%3},[%4];\n"
                 : "=r"(r[0]), "=r"(r[1]), "=r"(r[2]), "=r"(r[3]) : "r"(a));
}
__device__ __forceinline__ void ldsm4t(uint32_t* r, uint32_t a) {
    asm volatile("ldmatrix.sync.aligned.m8n8.x4.trans.shared.b16 {%0,%1,%2,%3},[%4];\n"
                 : "=r"(r[0]), "=r"(r[1]), "=r"(r[2]), "=r"(r[3]) : "r"(a));
}
__device__ __forceinline__ void mma16816(float* d, const uint32_t* a, uint32_t b0, uint32_t b1) {
    asm volatile("mma.sync.aligned.m16n8k16.row.col.f32.f16.f16.f32 "
                 "{%0,%1,%2,%3},{%4,%5,%6,%7},{%8,%9},{%0,%1,%2,%3};\n"
                 : "+f"(d[0]), "+f"(d[1]), "+f"(d[2]), "+f"(d[3])
                 : "r"(a[0]), "r"(a[1]), "r"(a[2]), "r"(a[3]), "r"(b0), "r"(b1));
}

// ---------------------------------------------------------------------------
// Setup: per-p scalars
// ---------------------------------------------------------------------------
__global__ void k_setup_small(const float* __restrict__ log_lambda_re,
                              const float* __restrict__ lambda_im,
                              const float* __restrict__ log_step) {
    int p = threadIdx.x;
    if (p >= PP) return;
    float lam_re = -expf(log_lambda_re[p]);
    float lam_im = lambda_im[p];
    float st = expf(log_step[p]);
    float ar = lam_re * st, ai = lam_im * st;
    float e = expf(ar);
    float lbr = e * cosf(ai);
    float lbi = e * sinf(ai);
    g_lbar[p] = lbr; g_lbar[PP + p] = lbi;
    float nr = lbr - 1.0f, ni = lbi;
    float d2 = lam_re * lam_re + lam_im * lam_im;
    g_coef[p]      = (nr * lam_re + ni * lam_im) / d2;
    g_coef[PP + p] = (ni * lam_re - nr * lam_im) / d2;
    float sr = lbr, si = lbi;
    #pragma unroll
    for (int i = 0; i < 7; i++) {
        float r2 = sr * sr - si * si;
        float i2 = 2.0f * sr * si;
        sr = r2; si = i2;
    }
    g_aC[p] = sr; g_aC[PP + p] = si;
}

// ---------------------------------------------------------------------------
// Setup: folded weights [k][n] row-major, fp16
// ---------------------------------------------------------------------------
__global__ void k_setup_W(const float* __restrict__ B_re, const float* __restrict__ B_im,
                          const float* __restrict__ C_re, const float* __restrict__ C_im) {
    int idx = blockIdx.x * blockDim.x + threadIdx.x;
    if (idx >= PP * HH) return;
    int p = idx / HH;
    int h = idx % HH;
    float cr = g_coef[p], ci = g_coef[PP + p];
    float br = B_re[p * HH + h], bi = B_im[p * HH + h];
    float w1r = cr * br - ci * bi;
    float w1i = cr * bi + ci * br;
    // GEMM1: k = h, n = p (re) / 256+p (im)
    g_W1[h * KK + p]      = __float2half_rn(w1r);
    g_W1[h * KK + PP + p] = __float2half_rn(w1i);
    // GEMM2: k = p (re) / 256+p (im), n = h
    g_W2[p * HH + h]        = __float2half_rn( 2.0f * C_re[h * PP + p]);
    g_W2[(PP + p) * HH + h] = __float2half_rn(-2.0f * C_im[h * PP + p]);
}

// ---------------------------------------------------------------------------
// fp16 tensor-core GEMM: C[M,512] = A[M,512] @ W[512,512]
// CONV: A fp32, converted in-kernel.  !CONV: A is fp16 already.
// Block 128x128x32, 256 threads, warp tile 64x32, 2 CTAs/SM.
// ---------------------------------------------------------------------------
template <bool CONV>
__global__ __launch_bounds__(256, 2) void k_gemm_f16(
    const float* __restrict__ Af,
    const __half* __restrict__ Ah,
    const __half* __restrict__ W,
    float* __restrict__ C)
{
    __shared__ __align__(16) __half Ash[BM * BKP];
    __shared__ __align__(16) __half Bsh[BK * BNP];

    int tid = threadIdx.x;
    int bx = blockIdx.x, by = blockIdx.y;
    int lane = tid & 31, wid = tid >> 5;
    int wm = (wid & 1) * 64;    // warp m offset
    int wn = (wid >> 1) * 32;   // warp n offset

    // gmem load indexing
    int arow = tid >> 3;           // fp32 A: 0..31 (+32 x4)
    int acol = (tid & 7) * 4;      // fp32 col (float4)
    int brow = tid >> 4;           // 0..15 (+16)
    int bcol = (tid & 15) * 8;     // fp16 col (8 elems)

    // ldmatrix per-lane element offsets
    int a_r = lane & 15;
    int a_c = (lane >> 4) * 8;
    int b_r = (lane & 7) + ((lane >> 3) & 1) * 8;
    int b_c = (lane >> 4) * 8;

    float acc[4][4][4];
    #pragma unroll
    for (int i = 0; i < 4; i++)
        #pragma unroll
        for (int j = 0; j < 4; j++)
            #pragma unroll
            for (int c = 0; c < 4; c++) acc[i][j][c] = 0.0f;

    for (int kt = 0; kt < KK; kt += BK) {
        // --- load A tile (128x32) ---
        if (CONV) {
            #pragma unroll
            for (int r = 0; r < 4; r++) {
                int row = arow + r * 32;
                float4 v = *reinterpret_cast<const float4*>(
                    &Af[(size_t)(by * BM + row) * KK + kt + acol]);
                __half2 h0 = __floats2half2_rn(v.x, v.y);
                __half2 h1 = __floats2half2_rn(v.z, v.w);
                uint32_t u0, u1;
                memcpy(&u0, &h0, 4); memcpy(&u1, &h1, 4);
                *reinterpret_cast<uint2*>(&Ash[row * BKP + acol]) = make_uint2(u0, u1);
            }
        } else {
            #pragma unroll
            for (int i2 = 0; i2 < 2; i2++) {
                int idx = tid + 256 * i2;       // 0..511
                int row = idx >> 2;             // 0..127
                int c8 = (idx & 3) * 8;         // 0,8,16,24
                float4 v = *reinterpret_cast<const float4*>(
                    &Ah[(size_t)(by * BM + row) * KK + kt + c8]);
                *reinterpret_cast<float4*>(&Ash[row * BKP + c8]) = v;
            }
        }
        // --- load B tile (32x128 fp16) ---
        #pragma unroll
        for (int r = 0; r < 2; r++) {
            int row = brow + r * 16;
            size_t go = (size_t)(kt + row) * 512 + bx * BN + bcol;
            *reinterpret_cast<float4*>(&Bsh[row * BNP + bcol]) =
                *reinterpret_cast<const float4*>(&W[go]);
        }
        __syncthreads();

        #pragma unroll
        for (int ks = 0; ks < BK; ks += 16) {
            uint32_t bf[2][4];
            #pragma unroll
            for (int j2 = 0; j2 < 2; j2++)
                ldsm4t(bf[j2], s2u(&Bsh[(ks + b_r) * BNP + wn + j2 * 16 + b_c]));
            #pragma unroll
            for (int i = 0; i < 4; i++) {
                uint32_t a[4];
                ldsm4(a, s2u(&Ash[(wm + i * 16 + a_r) * BKP + ks + a_c]));
                #pragma unroll
                for (int j = 0; j < 4; j++)
                    mma16816(acc[i][j], a, bf[j >> 1][(j & 1) * 2], bf[j >> 1][(j & 1) * 2 + 1]);
            }
        }
        __syncthreads();
    }

    // --- store C (fp32) ---
    #pragma unroll
    for (int i = 0; i < 4; i++) {
        int r0 = by * BM + wm + i * 16 + (lane >> 2);
        int c0 = bx * BN + wn + (lane & 3) * 2;
        #pragma unroll
        for (int j = 0; j < 4; j++) {
            *reinterpret_cast<float2*>(&C[(size_t)r0 * 512 + c0 + j * 8]) =
                make_float2(acc[i][j][0], acc[i][j][1]);
            *reinterpret_cast<float2*>(&C[(size_t)(r0 + 8) * 512 + c0 + j * 8]) =
                make_float2(acc[i][j][2], acc[i][j][3]);
        }
    }
}

// ---------------------------------------------------------------------------
// Scan phase 1: per-chunk carry (read-only over Bu)
// ---------------------------------------------------------------------------
__global__ __launch_bounds__(256) void k_scan_carry() {
    int blk = blockIdx.x;
    int b = blk / NCHUNK;
    int j = blk % NCHUNK;
    int p = threadIdx.x;
    float ar = g_lbar[p], ai = g_lbar[PP + p];
    float sr = 0.0f, si = 0.0f;
    size_t base = ((size_t)b * LL + (size_t)j * CH) * KK + p;
    #pragma unroll 4
    for (int t = 0; t < CH; t++) {
        float br = g_A1[base + (size_t)t * KK];
        float bi = g_A1[base + (size_t)t * KK + PP];
        float nr = fmaf(ar, sr, fmaf(-ai, si, br));
        float ni = fmaf(ar, si, fmaf(ai, sr, bi));
        sr = nr; si = ni;
    }
    g_carry[(size_t)blk * KK + p]      = sr;
    g_carry[(size_t)blk * KK + PP + p] = si;
}

// ---------------------------------------------------------------------------
// Scan phase 2: prefix over chunk carries (tiny)
// ---------------------------------------------------------------------------
__global__ void k_scan_prefix() {
    int b = blockIdx.x;
    int p = threadIdx.x;
    float ar = g_aC[p], ai = g_aC[PP + p];
    float sr = 0.0f, si = 0.0f;
    for (int j = 0; j < NCHUNK; j++) {
        size_t o = (size_t)(b * NCHUNK + j) * KK + p;
        g_prefix[o]      = sr;
        g_prefix[o + PP] = si;
        float cr = g_carry[o], ci = g_carry[o + PP];
        float nr = fmaf(ar, sr, fmaf(-ai, si, cr));
        float ni = fmaf(ar, si, fmaf(ai, sr, ci));
        sr = nr; si = ni;
    }
}

// ---------------------------------------------------------------------------
// Scan phase 3: recompute seeded with prefix, write xs as fp16
// ---------------------------------------------------------------------------
__global__ __launch_bounds__(256) void k_scan_apply() {
    int blk = blockIdx.x;
    int b = blk / NCHUNK;
    int j = blk % NCHUNK;
    int p = threadIdx.x;
    float ar = g_lbar[p], ai = g_lbar[PP + p];
    size_t po = (size_t)blk * KK + p;
    float sr = g_prefix[po], si = g_prefix[po + PP];
    size_t base = ((size_t)b * LL + (size_t)j * CH) * KK + p;
    #pragma unroll 4
    for (int t = 0; t < CH; t++) {
        float br = g_A1[base + (size_t)t * KK];
        float bi = g_A1[base + (size_t)t * KK + PP];
        float nr = fmaf(ar, sr, fmaf(-ai, si, br));
        float ni = fmaf(ar, si, fmaf(ai, sr, bi));
        sr = nr; si = ni;
        size_t o = base + (size_t)t * KK;
        g_XS[o]      = __float2half_rn(sr);
        g_XS[o + PP] = __float2half_rn(si);
    }
}

// ---------------------------------------------------------------------------
// Epilogue: y = gelu_tanh(ys + x*D); z = x + y; LayerNorm over H
// ---------------------------------------------------------------------------
__global__ __launch_bounds__(256) void k_epilogue(const float* __restrict__ x,
                                                  const float* __restrict__ D,
                                                  const float* __restrict__ ln_scale,
                                                  const float* __restrict__ ln_bias,
                                                  float* __restrict__ out) {
    int row = blockIdx.x;
    int tid = threadIdx.x;
    const float* ysr = g_ys + (size_t)row * HH;
    const float* xr  = x    + (size_t)row * HH;
    float zv[2];
    float sum = 0.0f, sum2 = 0.0f;
    #pragma unroll
    for (int e = 0; e < 2; e++) {
        int h = tid + e * 256;
        float xv = xr[h];
        float y = ysr[h] + xv * D[h];
        float y3 = y * y * y;
        float u = 0.7978845608028654f * (y + 0.044715f * y3);
        float g = 0.5f * y * (1.0f + tanhf(u));
        float z = xv + g;
        zv[e] = z;
        sum += z; sum2 += z * z;
    }
    __shared__ float s1[8], s2[8], stats[2];
    #pragma unroll
    for (int off = 16; off > 0; off >>= 1) {
        sum  += __shfl_down_sync(0xFFFFFFFFu, sum, off);
        sum2 += __shfl_down_sync(0xFFFFFFFFu, sum2, off);
    }
    int lane = tid & 31, wid = tid >> 5;
    if (lane == 0) { s1[wid] = sum; s2[wid] = sum2; }
    __syncthreads();
    if (tid == 0) {
        float a = 0.0f, b = 0.0f;
        #pragma unroll
        for (int i = 0; i < 8; i++) { a += s1[i]; b += s2[i]; }
        float mean = a * (1.0f / HH);
        float var = b * (1.0f / HH) - mean * mean;
        stats[0] = mean;
        stats[1] = rsqrtf(var + LN_EPS);
    }
    __syncthreads();
    float mean = stats[0], rstd = stats[1];
    float* outr = out + (size_t)row * HH;
    #pragma unroll
    for (int e = 0; e < 2; e++) {
        int h = tid + e * 256;
        outr[h] = (zv[e] - mean) * rstd * ln_scale[h] + ln_bias[h];
    }
}

// ---------------------------------------------------------------------------
// Launch
// ---------------------------------------------------------------------------
extern "C" void kernel_launch(void* const* d_in, const int* in_sizes, int n_in,
                              void* d_out, int out_size) {
    const float* x             = (const float*)d_in[0];
    const float* log_lambda_re = (const float*)d_in[1];
    const float* lambda_im     = (const float*)d_in[2];
    const float* B_re          = (const float*)d_in[3];
    const float* B_im          = (const float*)d_in[4];
    const float* C_re          = (const float*)d_in[5];
    const float* C_im          = (const float*)d_in[6];
    const float* D             = (const float*)d_in[7];
    const float* log_step      = (const float*)d_in[8];
    const float* ln_scale      = (const float*)d_in[9];
    const float* ln_bias       = (const float*)d_in[10];
    float* out = (float*)d_out;

    k_setup_small<<<1, 256>>>(log_lambda_re, lambda_im, log_step);
    k_setup_W<<<(PP * HH + 255) / 256, 256>>>(B_re, B_im, C_re, C_im);

    float *gA1, *gys;
    __half *gXS, *gW1, *gW2;
    cudaGetSymbolAddress((void**)&gA1, g_A1);
    cudaGetSymbolAddress((void**)&gys, g_ys);
    cudaGetSymbolAddress((void**)&gXS, g_XS);
    cudaGetSymbolAddress((void**)&gW1, g_W1);
    cudaGetSymbolAddress((void**)&gW2, g_W2);

    dim3 grid(HH / BN, MM / BM);   // (4, 512)

    // GEMM1: Bu = x @ W1 (A fp32, converted in-kernel)
    k_gemm_f16<true><<<grid, 256>>>(x, nullptr, gW1, gA1);

    // chunked scan over L (emits xs fp16)
    k_scan_carry<<<BB * NCHUNK, 256>>>();
    k_scan_prefix<<<BB, 256>>>();
    k_scan_apply<<<BB * NCHUNK, 256>>>();

    // GEMM2: ys = xs @ W2 (A fp16)
    k_gemm_f16<false><<<grid, 256>>>(nullptr, gXS, gW2, gys);

    // epilogue
    k_epilogue<<<MM, 256>>>(x, D, ln_scale, ln_bias, out);
}

// round 6
// speedup vs baseline: 1.7855x; 1.1165x over previous
#include <cuda_runtime.h>
#include <cuda_fp16.h>
#include <math.h>
#include <stdint.h>
#include <string.h>

// ---------------------------------------------------------------------------
// Problem constants
// ---------------------------------------------------------------------------
#define BB 16
#define LL 4096
#define HH 512
#define PP 256
#define MM (BB * LL)          // 65536 rows
#define KK 512                // GEMM K for both GEMMs
#define CH 128                // scan chunk length
#define NCHUNK (LL / CH)      // 32
#define LN_EPS 1e-6f

// GEMM tiling
#define BM 128
#define BN 128
#define BK 64
#define BKP 72    // padded A smem k-stride (fp16 elems) -> 144B rows, conflict-free
#define BNP 136   // padded B smem n-stride (fp16 elems) -> 272B rows, conflict-free

// ---------------------------------------------------------------------------
// Scratch (static __device__ — no allocation allowed)
// Layout: interleaved complex — col 2p = re, col 2p+1 = im.
// ---------------------------------------------------------------------------
__device__ __half g_Bu[(size_t)MM * KK];   // Bu (fp16, GEMM1 output, interleaved)
__device__ __half g_XS[(size_t)MM * KK];   // xs (fp16, interleaved)
__device__ __half g_ysh[(size_t)MM * HH];  // ys (fp16, GEMM2 output)
__device__ __half g_W1[KK * HH];           // W1 [k=h][n: 2p=re, 2p+1=im]
__device__ __half g_W2[KK * HH];           // W2 [k: 2p=re, 2p+1=im][n=h]
__device__ float g_lbar[2 * PP];
__device__ float g_aC[2 * PP];
__device__ float g_coef[2 * PP];
__device__ float g_carry[BB * NCHUNK * 2 * PP];    // (blk*256+p)*2 -> re,im
__device__ float g_prefix[BB * NCHUNK * 2 * PP];

// ---------------------------------------------------------------------------
// PTX helpers
// ---------------------------------------------------------------------------
__device__ __forceinline__ uint32_t s2u(const void* p) {
    return (uint32_t)__cvta_generic_to_shared(p);
}
__device__ __forceinline__ void ldsm4(uint32_t* r, uint32_t a) {
    asm volatile("ldmatrix.sync.aligned.m8n8.x4.shared.b16 {%0,%1,%2,%3},[%4];\n"
                 : "=r"(r[0]), "=r"(r[1]), "=r"(r[2]), "=r"(r[3]) : "r"(a));
}
__device__ __forceinline__ void ldsm4t(uint32_t* r, uint32_t a) {
    asm volatile("ldmatrix.sync.aligned.m8n8.x4.trans.shared.b16 {%0,%1,%2,%3},[%4];\n"
                 : "=r"(r[0]), "=r"(r[1]), "=r"(r[2]), "=r"(r[3]) : "r"(a));
}
__device__ __forceinline__ void mma16816(float* d, const uint32_t* a, uint32_t b0, uint32_t b1) {
    asm volatile("mma.sync.aligned.m16n8k16.row.col.f32.f16.f16.f32 "
                 "{%0,%1,%2,%3},{%4,%5,%6,%7},{%8,%9},{%0,%1,%2,%3};\n"
                 : "+f"(d[0]), "+f"(d[1]), "+f"(d[2]), "+f"(d[3])
                 : "r"(a[0]), "r"(a[1]), "r"(a[2]), "r"(a[3]), "r"(b0), "r"(b1));
}

// ---------------------------------------------------------------------------
// Setup: per-p scalars
// ---------------------------------------------------------------------------
__global__ void k_setup_small(const float* __restrict__ log_lambda_re,
                              const float* __restrict__ lambda_im,
                              const float* __restrict__ log_step) {
    int p = threadIdx.x;
    if (p >= PP) return;
    float lam_re = -expf(log_lambda_re[p]);
    float lam_im = lambda_im[p];
    float st = expf(log_step[p]);
    float ar = lam_re * st, ai = lam_im * st;
    float e = expf(ar);
    float lbr = e * cosf(ai);
    float lbi = e * sinf(ai);
    g_lbar[p] = lbr; g_lbar[PP + p] = lbi;
    float nr = lbr - 1.0f, ni = lbi;
    float d2 = lam_re * lam_re + lam_im * lam_im;
    g_coef[p]      = (nr * lam_re + ni * lam_im) / d2;
    g_coef[PP + p] = (ni * lam_re - nr * lam_im) / d2;
    float sr = lbr, si = lbi;
    #pragma unroll
    for (int i = 0; i < 7; i++) {
        float r2 = sr * sr - si * si;
        float i2 = 2.0f * sr * si;
        sr = r2; si = i2;
    }
    g_aC[p] = sr; g_aC[PP + p] = si;
}

// ---------------------------------------------------------------------------
// Setup: folded weights [k][n] row-major, fp16, interleaved complex columns
// ---------------------------------------------------------------------------
__global__ void k_setup_W(const float* __restrict__ B_re, const float* __restrict__ B_im,
                          const float* __restrict__ C_re, const float* __restrict__ C_im) {
    int idx = blockIdx.x * blockDim.x + threadIdx.x;
    if (idx >= PP * HH) return;
    int p = idx / HH;
    int h = idx % HH;
    float cr = g_coef[p], ci = g_coef[PP + p];
    float br = B_re[p * HH + h], bi = B_im[p * HH + h];
    float w1r = cr * br - ci * bi;
    float w1i = cr * bi + ci * br;
    // GEMM1: k = h, n = 2p (re) / 2p+1 (im)
    g_W1[h * KK + 2 * p]     = __float2half_rn(w1r);
    g_W1[h * KK + 2 * p + 1] = __float2half_rn(w1i);
    // GEMM2: k = 2p (re) / 2p+1 (im), n = h
    g_W2[(2 * p) * HH + h]     = __float2half_rn( 2.0f * C_re[h * PP + p]);
    g_W2[(2 * p + 1) * HH + h] = __float2half_rn(-2.0f * C_im[h * PP + p]);
}

// ---------------------------------------------------------------------------
// fp16 tensor-core GEMM: C[M,512] = A[M,512] @ W[512,512], C in fp16.
// CONV: A fp32, converted in-kernel.  !CONV: A is fp16 already.
// Block 128x128x64, 256 threads, warp tile 64x32, 2 CTAs/SM.
// ---------------------------------------------------------------------------
template <bool CONV>
__global__ __launch_bounds__(256, 2) void k_gemm_f16(
    const float* __restrict__ Af,
    const __half* __restrict__ Ah,
    const __half* __restrict__ W,
    __half* __restrict__ C)
{
    __shared__ __align__(16) __half Ash[BM * BKP];
    __shared__ __align__(16) __half Bsh[BK * BNP];

    int tid = threadIdx.x;
    int bx = blockIdx.x, by = blockIdx.y;
    int lane = tid & 31, wid = tid >> 5;
    int wm = (wid & 1) * 64;    // warp m offset
    int wn = (wid >> 1) * 32;   // warp n offset

    // ldmatrix per-lane element offsets
    int a_r = lane & 15;
    int a_c = (lane >> 4) * 8;
    int b_r = (lane & 7) + ((lane >> 3) & 1) * 8;
    int b_c = (lane >> 4) * 8;

    float acc[4][4][4];
    #pragma unroll
    for (int i = 0; i < 4; i++)
        #pragma unroll
        for (int j = 0; j < 4; j++)
            #pragma unroll
            for (int c = 0; c < 4; c++) acc[i][j][c] = 0.0f;

    for (int kt = 0; kt < KK; kt += BK) {
        // --- load A tile (128x64) ---
        if (CONV) {
            int row0 = tid >> 4;          // 0..15
            int col4 = (tid & 15) * 4;    // 0..60 (float4)
            #pragma unroll
            for (int r = 0; r < 8; r++) {
                int row = row0 + r * 16;
                float4 v = *reinterpret_cast<const float4*>(
                    &Af[(size_t)(by * BM + row) * KK + kt + col4]);
                __half2 h0 = __floats2half2_rn(v.x, v.y);
                __half2 h1 = __floats2half2_rn(v.z, v.w);
                uint32_t u0, u1;
                memcpy(&u0, &h0, 4); memcpy(&u1, &h1, 4);
                *reinterpret_cast<uint2*>(&Ash[row * BKP + col4]) = make_uint2(u0, u1);
            }
        } else {
            #pragma unroll
            for (int i2 = 0; i2 < 4; i2++) {
                int cidx = tid + 256 * i2;      // 0..1023
                int row = cidx >> 3;            // 0..127
                int c8 = (cidx & 7) * 8;        // 0..56
                float4 v = *reinterpret_cast<const float4*>(
                    &Ah[(size_t)(by * BM + row) * KK + kt + c8]);
                *reinterpret_cast<float4*>(&Ash[row * BKP + c8]) = v;
            }
        }
        // --- load B tile (64x128 fp16) ---
        #pragma unroll
        for (int i2 = 0; i2 < 4; i2++) {
            int cidx = tid + 256 * i2;          // 0..1023
            int row = cidx >> 4;                // 0..63
            int c8 = (cidx & 15) * 8;           // 0..120
            size_t go = (size_t)(kt + row) * 512 + bx * BN + c8;
            *reinterpret_cast<float4*>(&Bsh[row * BNP + c8]) =
                *reinterpret_cast<const float4*>(&W[go]);
        }
        __syncthreads();

        #pragma unroll
        for (int ks = 0; ks < BK; ks += 16) {
            uint32_t bf[2][4];
            #pragma unroll
            for (int j2 = 0; j2 < 2; j2++)
                ldsm4t(bf[j2], s2u(&Bsh[(ks + b_r) * BNP + wn + j2 * 16 + b_c]));
            #pragma unroll
            for (int i = 0; i < 4; i++) {
                uint32_t a[4];
                ldsm4(a, s2u(&Ash[(wm + i * 16 + a_r) * BKP + ks + a_c]));
                #pragma unroll
                for (int j = 0; j < 4; j++)
                    mma16816(acc[i][j], a, bf[j >> 1][(j & 1) * 2], bf[j >> 1][(j & 1) * 2 + 1]);
            }
        }
        __syncthreads();
    }

    // --- store C (fp16) ---
    #pragma unroll
    for (int i = 0; i < 4; i++) {
        int r0 = by * BM + wm + i * 16 + (lane >> 2);
        int c0 = bx * BN + wn + (lane & 3) * 2;
        #pragma unroll
        for (int j = 0; j < 4; j++) {
            *reinterpret_cast<__half2*>(&C[(size_t)r0 * 512 + c0 + j * 8]) =
                __floats2half2_rn(acc[i][j][0], acc[i][j][1]);
            *reinterpret_cast<__half2*>(&C[(size_t)(r0 + 8) * 512 + c0 + j * 8]) =
                __floats2half2_rn(acc[i][j][2], acc[i][j][3]);
        }
    }
}

// ---------------------------------------------------------------------------
// Scan phase 1: per-chunk carry (read-only over Bu, half2 interleaved)
// ---------------------------------------------------------------------------
__global__ __launch_bounds__(256) void k_scan_carry() {
    int blk = blockIdx.x;
    int b = blk / NCHUNK;
    int j = blk % NCHUNK;
    int p = threadIdx.x;
    float ar = g_lbar[p], ai = g_lbar[PP + p];
    float sr = 0.0f, si = 0.0f;
    const __half2* bu = reinterpret_cast<const __half2*>(g_Bu);
    size_t base = ((size_t)b * LL + (size_t)j * CH) * PP + p;
    #pragma unroll 4
    for (int t = 0; t < CH; t++) {
        float2 v = __half22float2(bu[base + (size_t)t * PP]);
        float nr = fmaf(ar, sr, fmaf(-ai, si, v.x));
        float ni = fmaf(ar, si, fmaf(ai, sr, v.y));
        sr = nr; si = ni;
    }
    g_carry[((size_t)blk * PP + p) * 2]     = sr;
    g_carry[((size_t)blk * PP + p) * 2 + 1] = si;
}

// ---------------------------------------------------------------------------
// Scan phase 2: prefix over chunk carries (tiny)
// ---------------------------------------------------------------------------
__global__ void k_scan_prefix() {
    int b = blockIdx.x;
    int p = threadIdx.x;
    float ar = g_aC[p], ai = g_aC[PP + p];
    float sr = 0.0f, si = 0.0f;
    for (int j = 0; j < NCHUNK; j++) {
        size_t o = ((size_t)(b * NCHUNK + j) * PP + p) * 2;
        g_prefix[o]     = sr;
        g_prefix[o + 1] = si;
        float cr = g_carry[o], ci = g_carry[o + 1];
        float nr = fmaf(ar, sr, fmaf(-ai, si, cr));
        float ni = fmaf(ar, si, fmaf(ai, sr, ci));
        sr = nr; si = ni;
    }
}

// ---------------------------------------------------------------------------
// Scan phase 3: recompute seeded with prefix, write xs as half2
// ---------------------------------------------------------------------------
__global__ __launch_bounds__(256) void k_scan_apply() {
    int blk = blockIdx.x;
    int b = blk / NCHUNK;
    int j = blk % NCHUNK;
    int p = threadIdx.x;
    float ar = g_lbar[p], ai = g_lbar[PP + p];
    size_t po = ((size_t)blk * PP + p) * 2;
    float sr = g_prefix[po], si = g_prefix[po + 1];
    const __half2* bu = reinterpret_cast<const __half2*>(g_Bu);
    __half2* xs = reinterpret_cast<__half2*>(g_XS);
    size_t base = ((size_t)b * LL + (size_t)j * CH) * PP + p;
    #pragma unroll 4
    for (int t = 0; t < CH; t++) {
        float2 v = __half22float2(bu[base + (size_t)t * PP]);
        float nr = fmaf(ar, sr, fmaf(-ai, si, v.x));
        float ni = fmaf(ar, si, fmaf(ai, sr, v.y));
        sr = nr; si = ni;
        xs[base + (size_t)t * PP] = __floats2half2_rn(sr, si);
    }
}

// ---------------------------------------------------------------------------
// Epilogue: y = gelu_tanh(ys + x*D); z = x + y; LayerNorm over H
// ---------------------------------------------------------------------------
__global__ __launch_bounds__(256) void k_epilogue(const float* __restrict__ x,
                                                  const float* __restrict__ D,
                                                  const float* __restrict__ ln_scale,
                                                  const float* __restrict__ ln_bias,
                                                  float* __restrict__ out) {
    int row = blockIdx.x;
    int tid = threadIdx.x;
    const __half2* ysr = reinterpret_cast<const __half2*>(g_ysh + (size_t)row * HH);
    const float2* xr = reinterpret_cast<const float2*>(x + (size_t)row * HH);
    const float2* D2 = reinterpret_cast<const float2*>(D);
    float zv[2];
    float sum = 0.0f, sum2 = 0.0f;
    {
        float2 ys2 = __half22float2(ysr[tid]);
        float2 xv = xr[tid];
        float2 dv = D2[tid];
        float yy[2] = {ys2.x + xv.x * dv.x, ys2.y + xv.y * dv.y};
        float xs[2] = {xv.x, xv.y};
        #pragma unroll
        for (int e = 0; e < 2; e++) {
            float y = yy[e];
            float y3 = y * y * y;
            float u = 0.7978845608028654f * (y + 0.044715f * y3);
            float g = 0.5f * y * (1.0f + tanhf(u));
            float z = xs[e] + g;
            zv[e] = z;
            sum += z; sum2 += z * z;
        }
    }
    __shared__ float s1[8], s2[8], stats[2];
    #pragma unroll
    for (int off = 16; off > 0; off >>= 1) {
        sum  += __shfl_down_sync(0xFFFFFFFFu, sum, off);
        sum2 += __shfl_down_sync(0xFFFFFFFFu, sum2, off);
    }
    int lane = tid & 31, wid = tid >> 5;
    if (lane == 0) { s1[wid] = sum; s2[wid] = sum2; }
    __syncthreads();
    if (tid == 0) {
        float a = 0.0f, b = 0.0f;
        #pragma unroll
        for (int i = 0; i < 8; i++) { a += s1[i]; b += s2[i]; }
        float mean = a * (1.0f / HH);
        float var = b * (1.0f / HH) - mean * mean;
        stats[0] = mean;
        stats[1] = rsqrtf(var + LN_EPS);
    }
    __syncthreads();
    float mean = stats[0], rstd = stats[1];
    const float2* sc2 = reinterpret_cast<const float2*>(ln_scale);
    const float2* bi2 = reinterpret_cast<const float2*>(ln_bias);
    float2 sc = sc2[tid], bi = bi2[tid];
    float2 o;
    o.x = (zv[0] - mean) * rstd * sc.x + bi.x;
    o.y = (zv[1] - mean) * rstd * sc.y + bi.y;
    reinterpret_cast<float2*>(out + (size_t)row * HH)[tid] = o;
}

// ---------------------------------------------------------------------------
// Launch
// ---------------------------------------------------------------------------
extern "C" void kernel_launch(void* const* d_in, const int* in_sizes, int n_in,
                              void* d_out, int out_size) {
    const float* x             = (const float*)d_in[0];
    const float* log_lambda_re = (const float*)d_in[1];
    const float* lambda_im     = (const float*)d_in[2];
    const float* B_re          = (const float*)d_in[3];
    const float* B_im          = (const float*)d_in[4];
    const float* C_re          = (const float*)d_in[5];
    const float* C_im          = (const float*)d_in[6];
    const float* D             = (const float*)d_in[7];
    const float* log_step      = (const float*)d_in[8];
    const float* ln_scale      = (const float*)d_in[9];
    const float* ln_bias       = (const float*)d_in[10];
    float* out = (float*)d_out;

    k_setup_small<<<1, 256>>>(log_lambda_re, lambda_im, log_step);
    k_setup_W<<<(PP * HH + 255) / 256, 256>>>(B_re, B_im, C_re, C_im);

    __half *gBu, *gXS, *gYS, *gW1, *gW2;
    cudaGetSymbolAddress((void**)&gBu, g_Bu);
    cudaGetSymbolAddress((void**)&gXS, g_XS);
    cudaGetSymbolAddress((void**)&gYS, g_ysh);
    cudaGetSymbolAddress((void**)&gW1, g_W1);
    cudaGetSymbolAddress((void**)&gW2, g_W2);

    dim3 grid(HH / BN, MM / BM);   // (4, 512)

    // GEMM1: Bu = x @ W1 (A fp32, converted in-kernel; out fp16 interleaved)
    k_gemm_f16<true><<<grid, 256>>>(x, nullptr, gW1, gBu);

    // chunked scan over L (half2 in, half2 out)
    k_scan_carry<<<BB * NCHUNK, 256>>>();
    k_scan_prefix<<<BB, 256>>>();
    k_scan_apply<<<BB * NCHUNK, 256>>>();

    // GEMM2: ys = xs @ W2 (A fp16; out fp16)
    k_gemm_f16<false><<<grid, 256>>>(nullptr, gXS, gW2, gYS);

    // epilogue
    k_epilogue<<<MM, 256>>>(x, D, ln_scale, ln_bias, out);
}

// round 7
// speedup vs baseline: 1.8116x; 1.0146x over previous
#include <cuda_runtime.h>
#include <cuda_fp16.h>
#include <math.h>
#include <stdint.h>
#include <string.h>

// ---------------------------------------------------------------------------
// Problem constants
// ---------------------------------------------------------------------------
#define BB 16
#define LL 4096
#define HH 512
#define PP 256
#define MM (BB * LL)          // 65536 rows
#define KK 512                // GEMM K
#define CH 128                // scan chunk length
#define NCHUNK (LL / CH)      // 32
#define LN_EPS 1e-6f

// GEMM tiling
#define BM 128
#define BN 128
#define BK 32
#define NIT (KK / BK)         // 16
#define BKP 40                // A smem k-stride (halves): 80B rows (16B aligned)
#define BNP 136               // B smem n-stride (halves): 272B rows (16B aligned)
// static smem layout (bytes)
#define SA0 0
#define SA1 10240
#define SB0 20480
#define SB1 29184
#define SM_BYTES 37888        // also holds 128x132 fp16 C tile (33792B) for fused scan
#define CT_STRIDE 66          // half2 per row (132 halves)

// ---------------------------------------------------------------------------
// Scratch (static __device__)
// Interleaved complex: col 2p = re, col 2p+1 = im.
// ---------------------------------------------------------------------------
__device__ __half g_Bu[(size_t)MM * KK];
__device__ __half g_XS[(size_t)MM * KK];
__device__ __half g_ysh[(size_t)MM * HH];
__device__ __half g_W1[KK * HH];
__device__ __half g_W2[KK * HH];
__device__ float g_lbar[2 * PP];
__device__ float g_a32[2 * PP];    // lbar^32
__device__ float g_aC[2 * PP];     // lbar^128
__device__ float g_coef[2 * PP];
__device__ float g_carry[BB * NCHUNK * 2 * PP];
__device__ float g_prefix[BB * NCHUNK * 2 * PP];

// ---------------------------------------------------------------------------
// PTX helpers
// ---------------------------------------------------------------------------
__device__ __forceinline__ uint32_t s2u(const void* p) {
    return (uint32_t)__cvta_generic_to_shared(p);
}
__device__ __forceinline__ void ldsm4(uint32_t* r, uint32_t a) {
    asm volatile("ldmatrix.sync.aligned.m8n8.x4.shared.b16 {%0,%1,%2,%3},[%4];\n"
                 : "=r"(r[0]), "=r"(r[1]), "=r"(r[2]), "=r"(r[3]) : "r"(a));
}
__device__ __forceinline__ void ldsm4t(uint32_t* r, uint32_t a) {
    asm volatile("ldmatrix.sync.aligned.m8n8.x4.trans.shared.b16 {%0,%1,%2,%3},[%4];\n"
                 : "=r"(r[0]), "=r"(r[1]), "=r"(r[2]), "=r"(r[3]) : "r"(a));
}
__device__ __forceinline__ void mma16816(float* d, const uint32_t* a, uint32_t b0, uint32_t b1) {
    asm volatile("mma.sync.aligned.m16n8k16.row.col.f32.f16.f16.f32 "
                 "{%0,%1,%2,%3},{%4,%5,%6,%7},{%8,%9},{%0,%1,%2,%3};\n"
                 : "+f"(d[0]), "+f"(d[1]), "+f"(d[2]), "+f"(d[3])
                 : "r"(a[0]), "r"(a[1]), "r"(a[2]), "r"(a[3]), "r"(b0), "r"(b1));
}
__device__ __forceinline__ void cp16(uint32_t dst, const void* src) {
    asm volatile("cp.async.cg.shared.global [%0], [%1], 16;" :: "r"(dst), "l"(src));
}
__device__ __forceinline__ void cp_commit() {
    asm volatile("cp.async.commit_group;" ::: "memory");
}
__device__ __forceinline__ void cp_wait0() {
    asm volatile("cp.async.wait_group 0;" ::: "memory");
}

// ---------------------------------------------------------------------------
// Setup: per-p scalars
// ---------------------------------------------------------------------------
__global__ void k_setup_small(const float* __restrict__ log_lambda_re,
                              const float* __restrict__ lambda_im,
                              const float* __restrict__ log_step) {
    int p = threadIdx.x;
    if (p >= PP) return;
    float lam_re = -expf(log_lambda_re[p]);
    float lam_im = lambda_im[p];
    float st = expf(log_step[p]);
    float ar = lam_re * st, ai = lam_im * st;
    float e = expf(ar);
    float lbr = e * cosf(ai);
    float lbi = e * sinf(ai);
    g_lbar[p] = lbr; g_lbar[PP + p] = lbi;
    float nr = lbr - 1.0f, ni = lbi;
    float d2 = lam_re * lam_re + lam_im * lam_im;
    g_coef[p]      = (nr * lam_re + ni * lam_im) / d2;
    g_coef[PP + p] = (ni * lam_re - nr * lam_im) / d2;
    float sr = lbr, si = lbi;
    #pragma unroll
    for (int i = 0; i < 5; i++) {          // ^32
        float r2 = sr * sr - si * si;
        float i2 = 2.0f * sr * si;
        sr = r2; si = i2;
    }
    g_a32[p] = sr; g_a32[PP + p] = si;
    #pragma unroll
    for (int i = 0; i < 2; i++) {          // ^128
        float r2 = sr * sr - si * si;
        float i2 = 2.0f * sr * si;
        sr = r2; si = i2;
    }
    g_aC[p] = sr; g_aC[PP + p] = si;
}

// ---------------------------------------------------------------------------
// Setup: folded weights [k][n], fp16, interleaved complex columns
// ---------------------------------------------------------------------------
__global__ void k_setup_W(const float* __restrict__ B_re, const float* __restrict__ B_im,
                          const float* __restrict__ C_re, const float* __restrict__ C_im) {
    int idx = blockIdx.x * blockDim.x + threadIdx.x;
    if (idx >= PP * HH) return;
    int p = idx / HH;
    int h = idx % HH;
    float cr = g_coef[p], ci = g_coef[PP + p];
    float br = B_re[p * HH + h], bi = B_im[p * HH + h];
    float w1r = cr * br - ci * bi;
    float w1i = cr * bi + ci * br;
    g_W1[h * KK + 2 * p]     = __float2half_rn(w1r);
    g_W1[h * KK + 2 * p + 1] = __float2half_rn(w1i);
    g_W2[(2 * p) * HH + h]     = __float2half_rn( 2.0f * C_re[h * PP + p]);
    g_W2[(2 * p + 1) * HH + h] = __float2half_rn(-2.0f * C_im[h * PP + p]);
}

// ---------------------------------------------------------------------------
// Pipelined fp16 GEMM, 2-stage cp.async, 2 CTAs/SM.
// CONV: A fp32 via LDG->regs->deferred STS.  !CONV: A fp16 via cp.async.
// FUSE: after store, compute scan-chunk carry from the C tile (GEMM1 only).
// ---------------------------------------------------------------------------
template <bool CONV, bool FUSE>
__global__ __launch_bounds__(256, 2) void k_gemm_f16(
    const float* __restrict__ Af,
    const __half* __restrict__ Ah,
    const __half* __restrict__ W,
    __half* __restrict__ C)
{
    __shared__ __align__(16) char sm[SM_BYTES];
    __shared__ float2 s_part[4][64];

    uint32_t smb = s2u(sm);
    int tid = threadIdx.x;
    int bx = blockIdx.x, by = blockIdx.y;
    int lane = tid & 31, wid = tid >> 5;
    int wm = (wid & 1) * 64;
    int wn = (wid >> 1) * 32;

    int a_r = lane & 15;
    int a_c = (lane >> 4) * 8;
    int b_r = (lane & 7) + ((lane >> 3) & 1) * 8;
    int b_c = (lane >> 4) * 8;

    float acc[4][4][4];
    #pragma unroll
    for (int i = 0; i < 4; i++)
        #pragma unroll
        for (int j = 0; j < 4; j++)
            #pragma unroll
            for (int c = 0; c < 4; c++) acc[i][j][c] = 0.0f;

    // load mappings
    int af_row = tid >> 3, af_col = (tid & 7) * 4;      // CONV A: 4 rows x float4
    float4 areg[4];

    const uint32_t sAoff[2] = {smb + SA0, smb + SA1};
    const uint32_t sBoff[2] = {smb + SB0, smb + SB1};

    auto cpB = [&](int it, uint32_t stage) {
        #pragma unroll
        for (int i = 0; i < 2; i++) {
            int cidx = tid + 256 * i;           // 0..511
            int row = cidx >> 4;                // 0..31
            int c16 = cidx & 15;
            cp16(stage + row * 272 + c16 * 16,
                 W + (size_t)(it * BK + row) * 512 + bx * BN + c16 * 8);
        }
    };
    auto cpA = [&](int it, uint32_t stage) {
        #pragma unroll
        for (int i = 0; i < 2; i++) {
            int cidx = tid + 256 * i;           // 0..511
            int row = cidx >> 2;                // 0..127
            int c16 = cidx & 3;
            cp16(stage + row * 80 + c16 * 16,
                 Ah + (size_t)(by * BM + row) * 512 + it * BK + c16 * 8);
        }
    };
    auto ldgA = [&](int it) {
        #pragma unroll
        for (int r = 0; r < 4; r++)
            areg[r] = *reinterpret_cast<const float4*>(
                Af + (size_t)(by * BM + af_row + r * 32) * 512 + it * BK + af_col);
    };
    auto stsA = [&](uint32_t stage) {
        #pragma unroll
        for (int r = 0; r < 4; r++) {
            float4 v = areg[r];
            __half2 h0 = __floats2half2_rn(v.x, v.y);
            __half2 h1 = __floats2half2_rn(v.z, v.w);
            uint32_t u0, u1;
            memcpy(&u0, &h0, 4); memcpy(&u1, &h1, 4);
            asm volatile("st.shared.v2.b32 [%0], {%1, %2};"
                :: "r"(stage + ((af_row + r * 32) * BKP + af_col) * 2), "r"(u0), "r"(u1)
                : "memory");
        }
    };

    // prologue: stage 0
    cpB(0, sBoff[0]);
    if (CONV) { ldgA(0); stsA(sAoff[0]); }
    else cpA(0, sAoff[0]);
    cp_commit();

    for (int it = 0; it < NIT; it++) {
        int s = it & 1;
        bool nxt = (it + 1 < NIT);
        cp_wait0();
        __syncthreads();
        if (nxt) {
            cpB(it + 1, sBoff[s ^ 1]);
            if (CONV) ldgA(it + 1);
            else cpA(it + 1, sAoff[s ^ 1]);
            cp_commit();
        }

        uint32_t sA = sAoff[s], sB = sBoff[s];
        #pragma unroll
        for (int ks = 0; ks < BK; ks += 16) {
            uint32_t bf[2][4];
            #pragma unroll
            for (int j2 = 0; j2 < 2; j2++)
                ldsm4t(bf[j2], sB + ((ks + b_r) * BNP + wn + j2 * 16 + b_c) * 2);
            #pragma unroll
            for (int i = 0; i < 4; i++) {
                uint32_t a[4];
                ldsm4(a, sA + ((wm + i * 16 + a_r) * BKP + ks + a_c) * 2);
                #pragma unroll
                for (int j = 0; j < 4; j++)
                    mma16816(acc[i][j], a, bf[j >> 1][(j & 1) * 2], bf[j >> 1][(j & 1) * 2 + 1]);
            }
        }
        if (nxt && CONV) stsA(sAoff[s ^ 1]);   // LDG overlapped with compute above
    }

    if (FUSE) __syncthreads();   // everyone done with stage smem before C-tile reuse
    __half2* Ct = reinterpret_cast<__half2*>(sm);

    // --- store C (fp16), optionally also to smem tile for fused scan ---
    #pragma unroll
    for (int i = 0; i < 4; i++) {
        int rl0 = wm + i * 16 + (lane >> 2);
        int r0 = by * BM + rl0;
        int cl0 = wn + (lane & 3) * 2;
        int c0 = bx * BN + cl0;
        #pragma unroll
        for (int j = 0; j < 4; j++) {
            __half2 v0 = __floats2half2_rn(acc[i][j][0], acc[i][j][1]);
            __half2 v1 = __floats2half2_rn(acc[i][j][2], acc[i][j][3]);
            *reinterpret_cast<__half2*>(&C[(size_t)r0 * 512 + c0 + j * 8]) = v0;
            *reinterpret_cast<__half2*>(&C[(size_t)(r0 + 8) * 512 + c0 + j * 8]) = v1;
            if (FUSE) {
                Ct[rl0 * CT_STRIDE + ((cl0 + j * 8) >> 1)] = v0;
                Ct[(rl0 + 8) * CT_STRIDE + ((cl0 + j * 8) >> 1)] = v1;
            }
        }
    }

    if (FUSE) {
        __syncthreads();
        // segmented scan over t=0..127 for 64 local p (global p = bx*64 + pl)
        int seg = tid >> 6;            // 0..3
        int pl = tid & 63;
        int pg = bx * 64 + pl;
        float ar = g_lbar[pg], ai = g_lbar[PP + pg];
        float sr = 0.0f, si = 0.0f;
        int t0 = seg * 32;
        #pragma unroll 4
        for (int t = t0; t < t0 + 32; t++) {
            float2 v = __half22float2(Ct[t * CT_STRIDE + pl]);
            float nr = fmaf(ar, sr, fmaf(-ai, si, v.x));
            float ni = fmaf(ar, si, fmaf(ai, sr, v.y));
            sr = nr; si = ni;
        }
        s_part[seg][pl] = make_float2(sr, si);
        __syncthreads();
        if (tid < 64) {
            int pg2 = bx * 64 + tid;
            float a32r = g_a32[pg2], a32i = g_a32[PP + pg2];
            float2 c = s_part[0][tid];
            #pragma unroll
            for (int k = 1; k < 4; k++) {
                float2 pk = s_part[k][tid];
                float cr = a32r * c.x - a32i * c.y + pk.x;
                float ci = a32r * c.y + a32i * c.x + pk.y;
                c.x = cr; c.y = ci;
            }
            size_t o = ((size_t)by * PP + pg2) * 2;   // blk == by (NCHUNK=32)
            g_carry[o] = c.x;
            g_carry[o + 1] = c.y;
        }
    }
}

// ---------------------------------------------------------------------------
// Scan phase 2: prefix over chunk carries (tiny)
// ---------------------------------------------------------------------------
__global__ void k_scan_prefix() {
    int b = blockIdx.x;
    int p = threadIdx.x;
    float ar = g_aC[p], ai = g_aC[PP + p];
    float sr = 0.0f, si = 0.0f;
    for (int j = 0; j < NCHUNK; j++) {
        size_t o = ((size_t)(b * NCHUNK + j) * PP + p) * 2;
        g_prefix[o]     = sr;
        g_prefix[o + 1] = si;
        float cr = g_carry[o], ci = g_carry[o + 1];
        float nr = fmaf(ar, sr, fmaf(-ai, si, cr));
        float ni = fmaf(ar, si, fmaf(ai, sr, ci));
        sr = nr; si = ni;
    }
}

// ---------------------------------------------------------------------------
// Scan phase 3: recompute seeded with prefix, write xs as half2
// ---------------------------------------------------------------------------
__global__ __launch_bounds__(256) void k_scan_apply() {
    int blk = blockIdx.x;
    int b = blk / NCHUNK;
    int j = blk % NCHUNK;
    int p = threadIdx.x;
    float ar = g_lbar[p], ai = g_lbar[PP + p];
    size_t po = ((size_t)blk * PP + p) * 2;
    float sr = g_prefix[po], si = g_prefix[po + 1];
    const __half2* bu = reinterpret_cast<const __half2*>(g_Bu);
    __half2* xs = reinterpret_cast<__half2*>(g_XS);
    size_t base = ((size_t)b * LL + (size_t)j * CH) * PP + p;
    #pragma unroll 4
    for (int t = 0; t < CH; t++) {
        float2 v = __half22float2(bu[base + (size_t)t * PP]);
        float nr = fmaf(ar, sr, fmaf(-ai, si, v.x));
        float ni = fmaf(ar, si, fmaf(ai, sr, v.y));
        sr = nr; si = ni;
        xs[base + (size_t)t * PP] = __floats2half2_rn(sr, si);
    }
}

// ---------------------------------------------------------------------------
// Epilogue: y = gelu_tanh(ys + x*D); z = x + y; LayerNorm over H
// ---------------------------------------------------------------------------
__global__ __launch_bounds__(256) void k_epilogue(const float* __restrict__ x,
                                                  const float* __restrict__ D,
                                                  const float* __restrict__ ln_scale,
                                                  const float* __restrict__ ln_bias,
                                                  float* __restrict__ out) {
    int row = blockIdx.x;
    int tid = threadIdx.x;
    const __half2* ysr = reinterpret_cast<const __half2*>(g_ysh + (size_t)row * HH);
    const float2* xr = reinterpret_cast<const float2*>(x + (size_t)row * HH);
    const float2* D2 = reinterpret_cast<const float2*>(D);
    float zv[2];
    float sum = 0.0f, sum2 = 0.0f;
    {
        float2 ys2 = __half22float2(ysr[tid]);
        float2 xv = xr[tid];
        float2 dv = D2[tid];
        float yy[2] = {ys2.x + xv.x * dv.x, ys2.y + xv.y * dv.y};
        float xs[2] = {xv.x, xv.y};
        #pragma unroll
        for (int e = 0; e < 2; e++) {
            float y = yy[e];
            float y3 = y * y * y;
            float u = 0.7978845608028654f * (y + 0.044715f * y3);
            float g = 0.5f * y * (1.0f + tanhf(u));
            float z = xs[e] + g;
            zv[e] = z;
            sum += z; sum2 += z * z;
        }
    }
    __shared__ float s1[8], s2[8], stats[2];
    #pragma unroll
    for (int off = 16; off > 0; off >>= 1) {
        sum  += __shfl_down_sync(0xFFFFFFFFu, sum, off);
        sum2 += __shfl_down_sync(0xFFFFFFFFu, sum2, off);
    }
    int lane = tid & 31, wid = tid >> 5;
    if (lane == 0) { s1[wid] = sum; s2[wid] = sum2; }
    __syncthreads();
    if (tid == 0) {
        float a = 0.0f, b = 0.0f;
        #pragma unroll
        for (int i = 0; i < 8; i++) { a += s1[i]; b += s2[i]; }
        float mean = a * (1.0f / HH);
        float var = b * (1.0f / HH) - mean * mean;
        stats[0] = mean;
        stats[1] = rsqrtf(var + LN_EPS);
    }
    __syncthreads();
    float mean = stats[0], rstd = stats[1];
    const float2* sc2 = reinterpret_cast<const float2*>(ln_scale);
    const float2* bi2 = reinterpret_cast<const float2*>(ln_bias);
    float2 sc = sc2[tid], bi = bi2[tid];
    float2 o;
    o.x = (zv[0] - mean) * rstd * sc.x + bi.x;
    o.y = (zv[1] - mean) * rstd * sc.y + bi.y;
    reinterpret_cast<float2*>(out + (size_t)row * HH)[tid] = o;
}

// ---------------------------------------------------------------------------
// Launch
// ---------------------------------------------------------------------------
extern "C" void kernel_launch(void* const* d_in, const int* in_sizes, int n_in,
                              void* d_out, int out_size) {
    const float* x             = (const float*)d_in[0];
    const float* log_lambda_re = (const float*)d_in[1];
    const float* lambda_im     = (const float*)d_in[2];
    const float* B_re          = (const float*)d_in[3];
    const float* B_im          = (const float*)d_in[4];
    const float* C_re          = (const float*)d_in[5];
    const float* C_im          = (const float*)d_in[6];
    const float* D             = (const float*)d_in[7];
    const float* log_step      = (const float*)d_in[8];
    const float* ln_scale      = (const float*)d_in[9];
    const float* ln_bias       = (const float*)d_in[10];
    float* out = (float*)d_out;

    k_setup_small<<<1, 256>>>(log_lambda_re, lambda_im, log_step);
    k_setup_W<<<(PP * HH + 255) / 256, 256>>>(B_re, B_im, C_re, C_im);

    __half *gBu, *gXS, *gYS, *gW1, *gW2;
    cudaGetSymbolAddress((void**)&gBu, g_Bu);
    cudaGetSymbolAddress((void**)&gXS, g_XS);
    cudaGetSymbolAddress((void**)&gYS, g_ysh);
    cudaGetSymbolAddress((void**)&gW1, g_W1);
    cudaGetSymbolAddress((void**)&gW2, g_W2);

    dim3 grid(HH / BN, MM / BM);   // (4, 512)

    // GEMM1: Bu = x @ W1 (fp32 A converted in-kernel) + fused chunk-carry
    k_gemm_f16<true, true><<<grid, 256>>>(x, nullptr, gW1, gBu);

    // scan: prefix over carries, then apply
    k_scan_prefix<<<BB, 256>>>();
    k_scan_apply<<<BB * NCHUNK, 256>>>();

    // GEMM2: ys = xs @ W2 (fp16 A via cp.async)
    k_gemm_f16<false, false><<<grid, 256>>>(nullptr, gXS, gW2, gYS);

    // epilogue
    k_epilogue<<<MM, 256>>>(x, D, ln_scale, ln_bias, out);
}